// round 4
// baseline (speedup 1.0000x reference)
#include <cuda_runtime.h>
#include <cuda_bf16.h>
#include <math.h>
#include <stdint.h>

// ---------------- problem constants ----------------
#define BATCH    2
#define SEQ      1024
#define DMODEL   1024
#define DINNER   2048
#define DSTATE   16
#define DTRANK   16
#define DCONV    4
#define MROWS    (BATCH * SEQ)          // 2048

// ---------------- scratch ----------------
__device__ float g_xres [MROWS * 2 * DINNER];
__device__ float g_xs   [MROWS * DINNER];
__device__ float g_xdbl [MROWS * (DTRANK + 2 * DSTATE)];
__device__ float g_delta[MROWS * DINNER];
__device__ float g_y    [MROWS * DINNER];       // rounded-to-tf32 at write
// pre-rounded GEMM operands
__device__ float g_x32  [MROWS * DMODEL];
__device__ float g_wi32 [2 * DINNER * DMODEL];
__device__ float g_wo32 [DMODEL * DINNER];

// ---------------- helpers ----------------
__device__ __forceinline__ uint32_t f2tf32(float f) {
    uint32_t u;
    asm("cvt.rna.tf32.f32 %0, %1;" : "=r"(u) : "f"(f));
    return u;
}
__device__ __forceinline__ float rnd_tf32(float f) {
    return __uint_as_float(f2tf32(f));
}
__device__ __forceinline__ uint32_t smem_u32(const void* p) {
    uint32_t a;
    asm("{ .reg .u64 t; cvta.to.shared.u64 t, %1; cvt.u32.u64 %0, t; }"
        : "=r"(a) : "l"(p));
    return a;
}
__device__ __forceinline__ void cp16(uint32_t dst, const void* src) {
    asm volatile("cp.async.cg.shared.global [%0], [%1], 16;"
                 :: "r"(dst), "l"(src) : "memory");
}
#define CP_COMMIT() asm volatile("cp.async.commit_group;" ::: "memory")
#define CP_WAIT1()  asm volatile("cp.async.wait_group 1;"  ::: "memory")

// ---------------- elementwise round-to-tf32 pre-pass -----------------------
__global__ void round_tf32_kernel(const float* __restrict__ in,
                                  float* __restrict__ out, int n4) {
    int i = blockIdx.x * blockDim.x + threadIdx.x;
    if (i >= n4) return;
    float4 v = ((const float4*)in)[i];
    v.x = rnd_tf32(v.x); v.y = rnd_tf32(v.y);
    v.z = rnd_tf32(v.z); v.w = rnd_tf32(v.w);
    ((float4*)out)[i] = v;
}

// ============================================================================
// TF32 mma.sync GEMM with cp.async 3-stage pipeline.
// C[M,N] = A[M,K] @ W[N,K]^T + bias. A, W MUST be pre-rounded to tf32.
// BM=BN=128, BK=32, 256 threads, warp tile 64x32 (m16n8k8).
// smem per stage: A 128x36 + B 128x36 floats (pad 4 -> conflict-free frags).
// ============================================================================
#define TSTR   36
#define TILE_B (128 * TSTR * 4)          // 18432 B
#define STG_B  (2 * TILE_B)              // 36864 B (A+B)
#define GEMM_SMEM (3 * STG_B)            // 110592 B

__global__ __launch_bounds__(256, 2)
void gemm_tf32_ca(const float* __restrict__ A, const float* __restrict__ W,
                  const float* __restrict__ bias, float* __restrict__ C,
                  int M, int N, int K) {
    extern __shared__ char smem[];
    const uint32_t sbase = smem_u32(smem);

    const int tid  = threadIdx.x;
    const int lane = tid & 31;
    const int wid  = tid >> 5;
    const int wm   = (wid & 1) * 64;
    const int wn   = (wid >> 1) * 32;
    const int grp  = lane >> 2;
    const int tig  = lane & 3;
    const int bm   = blockIdx.y * 128;
    const int bn   = blockIdx.x * 128;
    const int nt   = K >> 5;

    // staging assignment: 4 (A) + 4 (B) cp.asyncs per thread
    const int sr = tid >> 1;             // rows 0..127 (2 threads per row)
    const int sj0 = (tid & 1) * 4;       // chunk 0..3 or 4..7

    float c[4][4][4];
#pragma unroll
    for (int i = 0; i < 4; i++)
#pragma unroll
        for (int j = 0; j < 4; j++)
#pragma unroll
            for (int q = 0; q < 4; q++) c[i][j][q] = 0.f;

    auto stage = [&](int slot, int kt) {
        const float* Ag = A + (size_t)(bm + sr) * K + kt * 32;
        const float* Bg = W + (size_t)(bn + sr) * K + kt * 32;
        uint32_t dA = sbase + slot * STG_B + sr * (TSTR * 4) + sj0 * 16;
        uint32_t dB = dA + TILE_B;
#pragma unroll
        for (int j = 0; j < 4; j++) {
            cp16(dA + j * 16, Ag + (sj0 + j) * 4);
            cp16(dB + j * 16, Bg + (sj0 + j) * 4);
        }
    };

    // prologue: stages 0,1
    stage(0, 0); CP_COMMIT();
    stage(1, 1); CP_COMMIT();

    for (int kt = 0; kt < nt; kt++) {
        CP_WAIT1();
        __syncthreads();
        const int slot = kt - (kt / 3) * 3;

        // issue loads for kt+2 into slot (kt+2)%3 (buffer freed at kt-1)
        if (kt + 2 < nt) stage((kt + 2) - ((kt + 2) / 3) * 3, kt + 2);
        CP_COMMIT();

        const uint32_t* pa = (const uint32_t*)(smem + slot * STG_B);
        const uint32_t* pb = pa + 128 * TSTR;

#pragma unroll
        for (int ks = 0; ks < 4; ks++) {
            const int k0 = ks * 8;
            uint32_t a[4][4], b[4][2];
#pragma unroll
            for (int mi = 0; mi < 4; mi++) {
                const int mr = wm + mi * 16;
                a[mi][0] = pa[(mr + grp)     * TSTR + k0 + tig];
                a[mi][1] = pa[(mr + grp + 8) * TSTR + k0 + tig];
                a[mi][2] = pa[(mr + grp)     * TSTR + k0 + tig + 4];
                a[mi][3] = pa[(mr + grp + 8) * TSTR + k0 + tig + 4];
            }
#pragma unroll
            for (int nj = 0; nj < 4; nj++) {
                const int nr = wn + nj * 8 + grp;
                b[nj][0] = pb[nr * TSTR + k0 + tig];
                b[nj][1] = pb[nr * TSTR + k0 + tig + 4];
            }
#pragma unroll
            for (int mi = 0; mi < 4; mi++)
#pragma unroll
                for (int nj = 0; nj < 4; nj++) {
                    asm volatile(
                        "mma.sync.aligned.m16n8k8.row.col.f32.tf32.tf32.f32 "
                        "{%0,%1,%2,%3},{%4,%5,%6,%7},{%8,%9},{%0,%1,%2,%3};\n"
                        : "+f"(c[mi][nj][0]), "+f"(c[mi][nj][1]),
                          "+f"(c[mi][nj][2]), "+f"(c[mi][nj][3])
                        : "r"(a[mi][0]), "r"(a[mi][1]), "r"(a[mi][2]), "r"(a[mi][3]),
                          "r"(b[nj][0]), "r"(b[nj][1]));
                }
        }
    }

    // epilogue: bias + store
#pragma unroll
    for (int nj = 0; nj < 4; nj++) {
        int n = bn + wn + nj * 8 + tig * 2;
        float bv0 = bias[n], bv1 = bias[n + 1];
#pragma unroll
        for (int mi = 0; mi < 4; mi++) {
            int m = bm + wm + mi * 16 + grp;
            float2 v0 = make_float2(c[mi][nj][0] + bv0, c[mi][nj][1] + bv1);
            float2 v1 = make_float2(c[mi][nj][2] + bv0, c[mi][nj][3] + bv1);
            *(float2*)(C + (size_t)m * N + n)       = v0;
            *(float2*)(C + (size_t)(m + 8) * N + n) = v1;
        }
    }
}

// ---------------- causal depthwise conv (d_conv=4) + SiLU ------------------
__global__ void conv_silu_kernel(const float* __restrict__ conv_w,
                                 const float* __restrict__ conv_b) {
    int idx = blockIdx.x * blockDim.x + threadIdx.x;
    if (idx >= MROWS * DINNER) return;
    int d = idx & (DINNER - 1);
    int m = idx >> 11;
    int t = m & (SEQ - 1);

    float4 w = *(const float4*)(conv_w + d * 4);
    float acc = conv_b[d];
    const float* src = g_xres + (size_t)m * (2 * DINNER) + d;
    if (t >= 3) acc = fmaf(w.x, src[-3 * 2 * DINNER], acc);
    if (t >= 2) acc = fmaf(w.y, src[-2 * 2 * DINNER], acc);
    if (t >= 1) acc = fmaf(w.z, src[-1 * 2 * DINNER], acc);
    acc = fmaf(w.w, src[0], acc);
    g_xs[idx] = acc / (1.f + __expf(-acc));
}

// ---------------- x_proj: [M,48] = xs[M,2048] @ W[48,2048]^T + b -----------
__global__ __launch_bounds__(256)
void xproj_kernel(const float* __restrict__ W,
                  const float* __restrict__ bias) {
    int lane = threadIdx.x & 31;
    int j    = blockIdx.x * 8 + (threadIdx.x >> 5);
    int m0   = blockIdx.y * 16;

    const float* wrow = W + (size_t)j * DINNER;
    float wr[64];
#pragma unroll
    for (int i = 0; i < 16; i++) {
        float4 v = *(const float4*)(wrow + lane * 4 + i * 128);
        wr[i * 4 + 0] = v.x; wr[i * 4 + 1] = v.y;
        wr[i * 4 + 2] = v.z; wr[i * 4 + 3] = v.w;
    }
    float bj = bias[j];

    for (int mi = 0; mi < 16; mi++) {
        const float* xrow = g_xs + (size_t)(m0 + mi) * DINNER;
        float acc = 0.f;
#pragma unroll
        for (int i = 0; i < 16; i++) {
            float4 x = *(const float4*)(xrow + lane * 4 + i * 128);
            acc = fmaf(x.x, wr[i * 4 + 0], acc);
            acc = fmaf(x.y, wr[i * 4 + 1], acc);
            acc = fmaf(x.z, wr[i * 4 + 2], acc);
            acc = fmaf(x.w, wr[i * 4 + 3], acc);
        }
#pragma unroll
        for (int off = 16; off > 0; off >>= 1)
            acc += __shfl_xor_sync(0xffffffffu, acc, off);
        if (lane == 0) g_xdbl[(size_t)(m0 + mi) * 48 + j] = acc + bj;
    }
}

// ---------------- dt_proj (K=16) + softplus --------------------------------
__global__ __launch_bounds__(256)
void dt_softplus_kernel(const float* __restrict__ Wdt,
                        const float* __restrict__ bdt) {
    __shared__ float xd[32][16];
    int d  = blockIdx.x * 256 + threadIdx.x;
    int m0 = blockIdx.y * 32;

    float w[16];
#pragma unroll
    for (int i = 0; i < 4; i++) {
        float4 v = *(const float4*)(Wdt + (size_t)d * 16 + i * 4);
        w[i * 4 + 0] = v.x; w[i * 4 + 1] = v.y;
        w[i * 4 + 2] = v.z; w[i * 4 + 3] = v.w;
    }
    float bias = bdt[d];

#pragma unroll
    for (int it = 0; it < 2; it++) {
        int lin = threadIdx.x + it * 256;
        int mi  = lin >> 4;
        int r   = lin & 15;
        xd[mi][r] = g_xdbl[(size_t)(m0 + mi) * 48 + r];
    }
    __syncthreads();

    for (int mi = 0; mi < 32; mi++) {
        float acc = bias;
#pragma unroll
        for (int r = 0; r < 16; r++) acc = fmaf(xd[mi][r], w[r], acc);
        float sp = (acc > 20.f) ? acc : log1pf(__expf(acc));
        g_delta[(size_t)(m0 + mi) * DINNER + d] = sp;
    }
}

// ---------------- selective scan + skip + gating ---------------------------
// output y rounded to tf32 (it is the next GEMM's A operand)
__global__ void scan_kernel(const float* __restrict__ A_log,
                            const float* __restrict__ Dp) {
    int tid = blockIdx.x * blockDim.x + threadIdx.x;
    int n = tid & 15;
    int c = tid >> 4;
    int d = c & (DINNER - 1);
    int b = c >> 11;

    float Aval = -__expf(A_log[d * DSTATE + n]);
    float Dv   = Dp[d];

    const float* dptr  = g_delta + (size_t)b * SEQ * DINNER + d;
    const float* xptr  = g_xs    + (size_t)b * SEQ * DINNER + d;
    const float* rptr  = g_xres  + (size_t)b * SEQ * (2 * DINNER) + DINNER + d;
    const float* bcptr = g_xdbl  + (size_t)b * SEQ * 48 + DTRANK + n;
    float*       yptr  = g_y     + (size_t)b * SEQ * DINNER + d;

    float h = 0.f;
    for (int t = 0; t < SEQ; t++) {
        float dt = __ldg(dptr);
        float xv = __ldg(xptr);
        float Bv = __ldg(bcptr);
        float Cv = __ldg(bcptr + DSTATE);

        float dA = __expf(dt * Aval);
        h = fmaf(dA, h, dt * xv * Bv);
        float p = h * Cv;
        p += __shfl_xor_sync(0xffffffffu, p, 1);
        p += __shfl_xor_sync(0xffffffffu, p, 2);
        p += __shfl_xor_sync(0xffffffffu, p, 4);
        p += __shfl_xor_sync(0xffffffffu, p, 8);

        if (n == 0) {
            float r = __ldg(rptr);
            float g = r / (1.f + __expf(-r));
            *yptr = rnd_tf32((p + xv * Dv) * g);
        }
        dptr += DINNER; xptr += DINNER; rptr += 2 * DINNER;
        bcptr += 48;    yptr += DINNER;
    }
}

// ---------------- launch ----------------------------------------------------
extern "C" void kernel_launch(void* const* d_in, const int* in_sizes, int n_in,
                              void* d_out, int out_size) {
    const float* x        = (const float*)d_in[0];
    const float* in_w     = (const float*)d_in[1];
    const float* in_b     = (const float*)d_in[2];
    const float* conv_w   = (const float*)d_in[3];
    const float* conv_b   = (const float*)d_in[4];
    const float* xproj_w  = (const float*)d_in[5];
    const float* xproj_b  = (const float*)d_in[6];
    const float* dt_w     = (const float*)d_in[7];
    const float* dt_b     = (const float*)d_in[8];
    const float* A_log    = (const float*)d_in[9];
    const float* Dp       = (const float*)d_in[10];
    const float* out_w    = (const float*)d_in[11];
    const float* out_b    = (const float*)d_in[12];
    float* out = (float*)d_out;

    float *p_xres, *p_y, *p_x32, *p_wi32, *p_wo32;
    cudaGetSymbolAddress((void**)&p_xres, g_xres);
    cudaGetSymbolAddress((void**)&p_y, g_y);
    cudaGetSymbolAddress((void**)&p_x32, g_x32);
    cudaGetSymbolAddress((void**)&p_wi32, g_wi32);
    cudaGetSymbolAddress((void**)&p_wo32, g_wo32);

    cudaFuncSetAttribute(gemm_tf32_ca,
                         cudaFuncAttributeMaxDynamicSharedMemorySize, GEMM_SMEM);

    // 0) pre-round GEMM operands to tf32
    {
        int n4;
        n4 = MROWS * DMODEL / 4;
        round_tf32_kernel<<<(n4 + 255) / 256, 256>>>(x, p_x32, n4);
        n4 = 2 * DINNER * DMODEL / 4;
        round_tf32_kernel<<<(n4 + 255) / 256, 256>>>(in_w, p_wi32, n4);
        n4 = DMODEL * DINNER / 4;
        round_tf32_kernel<<<(n4 + 255) / 256, 256>>>(out_w, p_wo32, n4);
    }
    // 1) in_proj: [2048, 4096] = x[2048,1024] @ in_w[4096,1024]^T
    {
        dim3 grid(2 * DINNER / 128, MROWS / 128);
        gemm_tf32_ca<<<grid, 256, GEMM_SMEM>>>(p_x32, p_wi32, in_b, p_xres,
                                               MROWS, 2 * DINNER, DMODEL);
    }
    // 2) conv + silu
    {
        int total = MROWS * DINNER;
        conv_silu_kernel<<<(total + 255) / 256, 256>>>(conv_w, conv_b);
    }
    // 3) x_proj -> [2048, 48]
    {
        dim3 grid(6, MROWS / 16);
        xproj_kernel<<<grid, 256>>>(xproj_w, xproj_b);
    }
    // 4) dt_proj + softplus
    {
        dim3 grid(DINNER / 256, MROWS / 32);
        dt_softplus_kernel<<<grid, 256>>>(dt_w, dt_b);
    }
    // 5) selective scan + skip + gating (writes tf32-rounded y)
    {
        scan_kernel<<<(BATCH * DINNER * DSTATE) / 256, 256>>>(A_log, Dp);
    }
    // 6) out_proj: [2048, 1024] = y[2048,2048] @ out_w[1024,2048]^T
    {
        dim3 grid(DMODEL / 128, MROWS / 128);
        gemm_tf32_ca<<<grid, 256, GEMM_SMEM>>>(p_y, p_wo32, out_b, out,
                                               MROWS, DMODEL, DINNER);
    }
}

// round 5
// speedup vs baseline: 1.9341x; 1.9341x over previous
#include <cuda_runtime.h>
#include <cuda_bf16.h>
#include <math.h>
#include <stdint.h>

// ---------------- problem constants ----------------
#define BATCH    2
#define SEQ      1024
#define DMODEL   1024
#define DINNER   2048
#define DSTATE   16
#define DTRANK   16
#define DCONV    4
#define MROWS    (BATCH * SEQ)          // 2048

// ---------------- scratch ----------------
__device__ float g_xres [MROWS * 2 * DINNER];
__device__ float g_xs   [MROWS * DINNER];
__device__ float g_xdbl [MROWS * (DTRANK + 2 * DSTATE)];
__device__ float g_delta[MROWS * DINNER];
__device__ float g_y    [MROWS * DINNER];       // rounded-to-tf32 at write
// pre-rounded GEMM operands
__device__ float g_x32  [MROWS * DMODEL];
__device__ float g_wi32 [2 * DINNER * DMODEL];
__device__ float g_wo32 [DMODEL * DINNER];

// ---------------- helpers ----------------
__device__ __forceinline__ uint32_t f2tf32(float f) {
    uint32_t u;
    asm("cvt.rna.tf32.f32 %0, %1;" : "=r"(u) : "f"(f));
    return u;
}
__device__ __forceinline__ float rnd_tf32(float f) {
    return __uint_as_float(f2tf32(f));
}
__device__ __forceinline__ uint32_t smem_u32(const void* p) {
    uint32_t a;
    asm("{ .reg .u64 t; cvta.to.shared.u64 t, %1; cvt.u32.u64 %0, t; }"
        : "=r"(a) : "l"(p));
    return a;
}
__device__ __forceinline__ void cp16(uint32_t dst, const void* src) {
    asm volatile("cp.async.cg.shared.global [%0], [%1], 16;"
                 :: "r"(dst), "l"(src) : "memory");
}
#define CP_COMMIT() asm volatile("cp.async.commit_group;" ::: "memory")
#define CP_WAIT1()  asm volatile("cp.async.wait_group 1;"  ::: "memory")

// ---------------- elementwise round-to-tf32 pre-pass -----------------------
__global__ void round_tf32_kernel(const float* __restrict__ in,
                                  float* __restrict__ out, int n4) {
    int i = blockIdx.x * blockDim.x + threadIdx.x;
    if (i >= n4) return;
    float4 v = ((const float4*)in)[i];
    v.x = rnd_tf32(v.x); v.y = rnd_tf32(v.y);
    v.z = rnd_tf32(v.z); v.w = rnd_tf32(v.w);
    ((float4*)out)[i] = v;
}

// ============================================================================
// TF32 mma.sync GEMM with cp.async 3-stage pipeline (unchanged from R4).
// ============================================================================
#define TSTR   36
#define TILE_B (128 * TSTR * 4)          // 18432 B
#define STG_B  (2 * TILE_B)              // 36864 B (A+B)
#define GEMM_SMEM (3 * STG_B)            // 110592 B

__global__ __launch_bounds__(256, 2)
void gemm_tf32_ca(const float* __restrict__ A, const float* __restrict__ W,
                  const float* __restrict__ bias, float* __restrict__ C,
                  int M, int N, int K) {
    extern __shared__ char smem[];
    const uint32_t sbase = smem_u32(smem);

    const int tid  = threadIdx.x;
    const int lane = tid & 31;
    const int wid  = tid >> 5;
    const int wm   = (wid & 1) * 64;
    const int wn   = (wid >> 1) * 32;
    const int grp  = lane >> 2;
    const int tig  = lane & 3;
    const int bm   = blockIdx.y * 128;
    const int bn   = blockIdx.x * 128;
    const int nt   = K >> 5;

    const int sr  = tid >> 1;
    const int sj0 = (tid & 1) * 4;

    float c[4][4][4];
#pragma unroll
    for (int i = 0; i < 4; i++)
#pragma unroll
        for (int j = 0; j < 4; j++)
#pragma unroll
            for (int q = 0; q < 4; q++) c[i][j][q] = 0.f;

    auto stage = [&](int slot, int kt) {
        const float* Ag = A + (size_t)(bm + sr) * K + kt * 32;
        const float* Bg = W + (size_t)(bn + sr) * K + kt * 32;
        uint32_t dA = sbase + slot * STG_B + sr * (TSTR * 4) + sj0 * 16;
        uint32_t dB = dA + TILE_B;
#pragma unroll
        for (int j = 0; j < 4; j++) {
            cp16(dA + j * 16, Ag + (sj0 + j) * 4);
            cp16(dB + j * 16, Bg + (sj0 + j) * 4);
        }
    };

    stage(0, 0); CP_COMMIT();
    stage(1, 1); CP_COMMIT();

    for (int kt = 0; kt < nt; kt++) {
        CP_WAIT1();
        __syncthreads();
        const int slot = kt - (kt / 3) * 3;

        if (kt + 2 < nt) stage((kt + 2) - ((kt + 2) / 3) * 3, kt + 2);
        CP_COMMIT();

        const uint32_t* pa = (const uint32_t*)(smem + slot * STG_B);
        const uint32_t* pb = pa + 128 * TSTR;

#pragma unroll
        for (int ks = 0; ks < 4; ks++) {
            const int k0 = ks * 8;
            uint32_t a[4][4], b[4][2];
#pragma unroll
            for (int mi = 0; mi < 4; mi++) {
                const int mr = wm + mi * 16;
                a[mi][0] = pa[(mr + grp)     * TSTR + k0 + tig];
                a[mi][1] = pa[(mr + grp + 8) * TSTR + k0 + tig];
                a[mi][2] = pa[(mr + grp)     * TSTR + k0 + tig + 4];
                a[mi][3] = pa[(mr + grp + 8) * TSTR + k0 + tig + 4];
            }
#pragma unroll
            for (int nj = 0; nj < 4; nj++) {
                const int nr = wn + nj * 8 + grp;
                b[nj][0] = pb[nr * TSTR + k0 + tig];
                b[nj][1] = pb[nr * TSTR + k0 + tig + 4];
            }
#pragma unroll
            for (int mi = 0; mi < 4; mi++)
#pragma unroll
                for (int nj = 0; nj < 4; nj++) {
                    asm volatile(
                        "mma.sync.aligned.m16n8k8.row.col.f32.tf32.tf32.f32 "
                        "{%0,%1,%2,%3},{%4,%5,%6,%7},{%8,%9},{%0,%1,%2,%3};\n"
                        : "+f"(c[mi][nj][0]), "+f"(c[mi][nj][1]),
                          "+f"(c[mi][nj][2]), "+f"(c[mi][nj][3])
                        : "r"(a[mi][0]), "r"(a[mi][1]), "r"(a[mi][2]), "r"(a[mi][3]),
                          "r"(b[nj][0]), "r"(b[nj][1]));
                }
        }
    }

#pragma unroll
    for (int nj = 0; nj < 4; nj++) {
        int n = bn + wn + nj * 8 + tig * 2;
        float bv0 = bias[n], bv1 = bias[n + 1];
#pragma unroll
        for (int mi = 0; mi < 4; mi++) {
            int m = bm + wm + mi * 16 + grp;
            float2 v0 = make_float2(c[mi][nj][0] + bv0, c[mi][nj][1] + bv1);
            float2 v1 = make_float2(c[mi][nj][2] + bv0, c[mi][nj][3] + bv1);
            *(float2*)(C + (size_t)m * N + n)       = v0;
            *(float2*)(C + (size_t)(m + 8) * N + n) = v1;
        }
    }
}

// ---------------- causal depthwise conv (d_conv=4) + SiLU ------------------
__global__ void conv_silu_kernel(const float* __restrict__ conv_w,
                                 const float* __restrict__ conv_b) {
    int idx = blockIdx.x * blockDim.x + threadIdx.x;
    if (idx >= MROWS * DINNER) return;
    int d = idx & (DINNER - 1);
    int m = idx >> 11;
    int t = m & (SEQ - 1);

    float4 w = *(const float4*)(conv_w + d * 4);
    float acc = conv_b[d];
    const float* src = g_xres + (size_t)m * (2 * DINNER) + d;
    if (t >= 3) acc = fmaf(w.x, src[-3 * 2 * DINNER], acc);
    if (t >= 2) acc = fmaf(w.y, src[-2 * 2 * DINNER], acc);
    if (t >= 1) acc = fmaf(w.z, src[-1 * 2 * DINNER], acc);
    acc = fmaf(w.w, src[0], acc);
    g_xs[idx] = acc / (1.f + __expf(-acc));
}

// ---------------- x_proj: [M,48] = xs[M,2048] @ W[48,2048]^T + b -----------
__global__ __launch_bounds__(256)
void xproj_kernel(const float* __restrict__ W,
                  const float* __restrict__ bias) {
    int lane = threadIdx.x & 31;
    int j    = blockIdx.x * 8 + (threadIdx.x >> 5);
    int m0   = blockIdx.y * 16;

    const float* wrow = W + (size_t)j * DINNER;
    float wr[64];
#pragma unroll
    for (int i = 0; i < 16; i++) {
        float4 v = *(const float4*)(wrow + lane * 4 + i * 128);
        wr[i * 4 + 0] = v.x; wr[i * 4 + 1] = v.y;
        wr[i * 4 + 2] = v.z; wr[i * 4 + 3] = v.w;
    }
    float bj = bias[j];

    for (int mi = 0; mi < 16; mi++) {
        const float* xrow = g_xs + (size_t)(m0 + mi) * DINNER;
        float acc = 0.f;
#pragma unroll
        for (int i = 0; i < 16; i++) {
            float4 x = *(const float4*)(xrow + lane * 4 + i * 128);
            acc = fmaf(x.x, wr[i * 4 + 0], acc);
            acc = fmaf(x.y, wr[i * 4 + 1], acc);
            acc = fmaf(x.z, wr[i * 4 + 2], acc);
            acc = fmaf(x.w, wr[i * 4 + 3], acc);
        }
#pragma unroll
        for (int off = 16; off > 0; off >>= 1)
            acc += __shfl_xor_sync(0xffffffffu, acc, off);
        if (lane == 0) g_xdbl[(size_t)(m0 + mi) * 48 + j] = acc + bj;
    }
}

// ---------------- dt_proj (K=16) + softplus --------------------------------
__global__ __launch_bounds__(256)
void dt_softplus_kernel(const float* __restrict__ Wdt,
                        const float* __restrict__ bdt) {
    __shared__ float xd[32][16];
    int d  = blockIdx.x * 256 + threadIdx.x;
    int m0 = blockIdx.y * 32;

    float w[16];
#pragma unroll
    for (int i = 0; i < 4; i++) {
        float4 v = *(const float4*)(Wdt + (size_t)d * 16 + i * 4);
        w[i * 4 + 0] = v.x; w[i * 4 + 1] = v.y;
        w[i * 4 + 2] = v.z; w[i * 4 + 3] = v.w;
    }
    float bias = bdt[d];

#pragma unroll
    for (int it = 0; it < 2; it++) {
        int lin = threadIdx.x + it * 256;
        int mi  = lin >> 4;
        int r   = lin & 15;
        xd[mi][r] = g_xdbl[(size_t)(m0 + mi) * 48 + r];
    }
    __syncthreads();

    for (int mi = 0; mi < 32; mi++) {
        float acc = bias;
#pragma unroll
        for (int r = 0; r < 16; r++) acc = fmaf(xd[mi][r], w[r], acc);
        float sp = (acc > 20.f) ? acc : log1pf(__expf(acc));
        g_delta[(size_t)(m0 + mi) * DINNER + d] = sp;
    }
}

// ============================================================================
// Chunked selective scan: one block per (b, d). 256 threads = 16 chunks x 16 n.
// Phase 1: per-chunk local scan -> (P = prod dA, h_local).
// Phase 2: 16-step sequential combine across chunks (16 threads) -> h_in.
// Phase 3: re-scan chunk from h_in, reduce over n, gate, write y (tf32).
// ============================================================================
#define CHUNK 64
#define NCHUNK (SEQ / CHUNK)   // 16

__global__ __launch_bounds__(256)
void scan_chunked_kernel(const float* __restrict__ A_log,
                         const float* __restrict__ Dp) {
    __shared__ float sP  [NCHUNK][16];
    __shared__ float sH  [NCHUNK][16];
    __shared__ float sHin[NCHUNK][16];

    const int bd = blockIdx.x;               // 0..4095
    const int d  = bd & (DINNER - 1);
    const int b  = bd >> 11;
    const int n  = threadIdx.x & 15;
    const int ck = threadIdx.x >> 4;         // chunk 0..15

    const float Aval = -__expf(A_log[d * DSTATE + n]);
    const float Dv   = Dp[d];

    const size_t mbase = (size_t)(b * SEQ + ck * CHUNK);
    const float* dbase = g_delta + mbase * DINNER + d;
    const float* xbase = g_xs    + mbase * DINNER + d;
    const float* bbase = g_xdbl  + mbase * 48 + DTRANK + n;

    // ---- phase 1: local scan (no outputs) ----
    float P = 1.f, hl = 0.f;
    {
        const float* dp = dbase; const float* xp = xbase; const float* bp = bbase;
#pragma unroll 4
        for (int i = 0; i < CHUNK; i++) {
            float dt = __ldg(dp), xv = __ldg(xp), Bv = __ldg(bp);
            float dA = __expf(dt * Aval);
            P *= dA;
            hl = fmaf(dA, hl, dt * xv * Bv);
            dp += DINNER; xp += DINNER; bp += 48;
        }
    }
    sP[ck][n] = P; sH[ck][n] = hl;
    __syncthreads();

    // ---- phase 2: combine across chunks ----
    if (threadIdx.x < 16) {
        const int nn = threadIdx.x;
        float h = 0.f;
#pragma unroll
        for (int c = 0; c < NCHUNK; c++) {
            sHin[c][nn] = h;
            h = fmaf(sP[c][nn], h, sH[c][nn]);
        }
    }
    __syncthreads();

    // ---- phase 3: re-scan with correct h_in, produce y ----
    float h = sHin[ck][n];
    {
        const float* dp = dbase; const float* xp = xbase; const float* bp = bbase;
        const float* rp = g_xres + mbase * (2 * DINNER) + DINNER + d;
        float*       yp = g_y    + mbase * DINNER + d;
#pragma unroll 4
        for (int i = 0; i < CHUNK; i++) {
            float dt = __ldg(dp), xv = __ldg(xp);
            float Bv = __ldg(bp), Cv = __ldg(bp + DSTATE);
            float dA = __expf(dt * Aval);
            h = fmaf(dA, h, dt * xv * Bv);
            float p = h * Cv;
            p += __shfl_xor_sync(0xffffffffu, p, 1);
            p += __shfl_xor_sync(0xffffffffu, p, 2);
            p += __shfl_xor_sync(0xffffffffu, p, 4);
            p += __shfl_xor_sync(0xffffffffu, p, 8);
            if (n == 0) {
                float r = __ldg(rp);
                float g = r / (1.f + __expf(-r));
                *yp = rnd_tf32((p + xv * Dv) * g);
            }
            dp += DINNER; xp += DINNER; bp += 48;
            rp += 2 * DINNER; yp += DINNER;
        }
    }
}

// ---------------- launch ----------------------------------------------------
extern "C" void kernel_launch(void* const* d_in, const int* in_sizes, int n_in,
                              void* d_out, int out_size) {
    const float* x        = (const float*)d_in[0];
    const float* in_w     = (const float*)d_in[1];
    const float* in_b     = (const float*)d_in[2];
    const float* conv_w   = (const float*)d_in[3];
    const float* conv_b   = (const float*)d_in[4];
    const float* xproj_w  = (const float*)d_in[5];
    const float* xproj_b  = (const float*)d_in[6];
    const float* dt_w     = (const float*)d_in[7];
    const float* dt_b     = (const float*)d_in[8];
    const float* A_log    = (const float*)d_in[9];
    const float* Dp       = (const float*)d_in[10];
    const float* out_w    = (const float*)d_in[11];
    const float* out_b    = (const float*)d_in[12];
    float* out = (float*)d_out;

    float *p_xres, *p_y, *p_x32, *p_wi32, *p_wo32;
    cudaGetSymbolAddress((void**)&p_xres, g_xres);
    cudaGetSymbolAddress((void**)&p_y, g_y);
    cudaGetSymbolAddress((void**)&p_x32, g_x32);
    cudaGetSymbolAddress((void**)&p_wi32, g_wi32);
    cudaGetSymbolAddress((void**)&p_wo32, g_wo32);

    cudaFuncSetAttribute(gemm_tf32_ca,
                         cudaFuncAttributeMaxDynamicSharedMemorySize, GEMM_SMEM);

    // 0) pre-round GEMM operands to tf32
    {
        int n4;
        n4 = MROWS * DMODEL / 4;
        round_tf32_kernel<<<(n4 + 255) / 256, 256>>>(x, p_x32, n4);
        n4 = 2 * DINNER * DMODEL / 4;
        round_tf32_kernel<<<(n4 + 255) / 256, 256>>>(in_w, p_wi32, n4);
        n4 = DMODEL * DINNER / 4;
        round_tf32_kernel<<<(n4 + 255) / 256, 256>>>(out_w, p_wo32, n4);
    }
    // 1) in_proj
    {
        dim3 grid(2 * DINNER / 128, MROWS / 128);
        gemm_tf32_ca<<<grid, 256, GEMM_SMEM>>>(p_x32, p_wi32, in_b, p_xres,
                                               MROWS, 2 * DINNER, DMODEL);
    }
    // 2) conv + silu
    {
        int total = MROWS * DINNER;
        conv_silu_kernel<<<(total + 255) / 256, 256>>>(conv_w, conv_b);
    }
    // 3) x_proj
    {
        dim3 grid(6, MROWS / 16);
        xproj_kernel<<<grid, 256>>>(xproj_w, xproj_b);
    }
    // 4) dt_proj + softplus
    {
        dim3 grid(DINNER / 256, MROWS / 32);
        dt_softplus_kernel<<<grid, 256>>>(dt_w, dt_b);
    }
    // 5) chunked selective scan + skip + gating (writes tf32-rounded y)
    {
        scan_chunked_kernel<<<BATCH * DINNER, 256>>>(A_log, Dp);
    }
    // 6) out_proj
    {
        dim3 grid(DMODEL / 128, MROWS / 128);
        gemm_tf32_ca<<<grid, 256, GEMM_SMEM>>>(p_y, p_wo32, out_b, out,
                                               MROWS, DMODEL, DINNER);
    }
}

// round 6
// speedup vs baseline: 2.6907x; 1.3912x over previous
#include <cuda_runtime.h>
#include <cuda_bf16.h>
#include <math.h>
#include <stdint.h>

// ---------------- problem constants ----------------
#define BATCH    2
#define SEQ      1024
#define DMODEL   1024
#define DINNER   2048
#define DSTATE   16
#define DTRANK   16
#define DCONV    4
#define MROWS    (BATCH * SEQ)          // 2048
#define CHUNK    64
#define NCHUNK   (SEQ / CHUNK)          // 16

// ---------------- scratch ----------------
__device__ float g_xres [MROWS * 2 * DINNER];
__device__ float g_xs   [MROWS * DINNER];
__device__ float g_xdbl [MROWS * (DTRANK + 2 * DSTATE)];
__device__ float g_delta[MROWS * DINNER];
__device__ float g_y    [MROWS * DINNER];
// pre-rounded GEMM operands
__device__ float g_x32  [MROWS * DMODEL];
__device__ float g_wi32 [2 * DINNER * DMODEL];
__device__ float g_wo32 [DMODEL * DINNER];
// scan chunk summaries: [(b*NCHUNK+ck)*DINNER + d]*16 + n
__device__ float g_P  [BATCH * NCHUNK * DINNER * DSTATE];
__device__ float g_H  [BATCH * NCHUNK * DINNER * DSTATE];
__device__ float g_Hin[BATCH * NCHUNK * DINNER * DSTATE];

// ---------------- helpers ----------------
__device__ __forceinline__ uint32_t f2tf32(float f) {
    uint32_t u;
    asm("cvt.rna.tf32.f32 %0, %1;" : "=r"(u) : "f"(f));
    return u;
}
__device__ __forceinline__ float rnd_tf32(float f) {
    return __uint_as_float(f2tf32(f));
}
__device__ __forceinline__ uint32_t smem_u32(const void* p) {
    uint32_t a;
    asm("{ .reg .u64 t; cvta.to.shared.u64 t, %1; cvt.u32.u64 %0, t; }"
        : "=r"(a) : "l"(p));
    return a;
}
__device__ __forceinline__ void cp16(uint32_t dst, const void* src) {
    asm volatile("cp.async.cg.shared.global [%0], [%1], 16;"
                 :: "r"(dst), "l"(src) : "memory");
}
#define CP_COMMIT() asm volatile("cp.async.commit_group;" ::: "memory")
#define CP_WAIT1()  asm volatile("cp.async.wait_group 1;"  ::: "memory")

// ---------------- elementwise round-to-tf32 pre-pass -----------------------
__global__ void round_tf32_kernel(const float* __restrict__ in,
                                  float* __restrict__ out, int n4) {
    int i = blockIdx.x * blockDim.x + threadIdx.x;
    if (i >= n4) return;
    float4 v = ((const float4*)in)[i];
    v.x = rnd_tf32(v.x); v.y = rnd_tf32(v.y);
    v.z = rnd_tf32(v.z); v.w = rnd_tf32(v.w);
    ((float4*)out)[i] = v;
}

// ============================================================================
// TF32 mma.sync GEMM with cp.async 3-stage pipeline (unchanged, proven).
// ============================================================================
#define TSTR   36
#define TILE_B (128 * TSTR * 4)
#define STG_B  (2 * TILE_B)
#define GEMM_SMEM (3 * STG_B)

__global__ __launch_bounds__(256, 2)
void gemm_tf32_ca(const float* __restrict__ A, const float* __restrict__ W,
                  const float* __restrict__ bias, float* __restrict__ C,
                  int M, int N, int K) {
    extern __shared__ char smem[];
    const uint32_t sbase = smem_u32(smem);

    const int tid  = threadIdx.x;
    const int lane = tid & 31;
    const int wid  = tid >> 5;
    const int wm   = (wid & 1) * 64;
    const int wn   = (wid >> 1) * 32;
    const int grp  = lane >> 2;
    const int tig  = lane & 3;
    const int bm   = blockIdx.y * 128;
    const int bn   = blockIdx.x * 128;
    const int nt   = K >> 5;

    const int sr  = tid >> 1;
    const int sj0 = (tid & 1) * 4;

    float c[4][4][4];
#pragma unroll
    for (int i = 0; i < 4; i++)
#pragma unroll
        for (int j = 0; j < 4; j++)
#pragma unroll
            for (int q = 0; q < 4; q++) c[i][j][q] = 0.f;

    auto stage = [&](int slot, int kt) {
        const float* Ag = A + (size_t)(bm + sr) * K + kt * 32;
        const float* Bg = W + (size_t)(bn + sr) * K + kt * 32;
        uint32_t dA = sbase + slot * STG_B + sr * (TSTR * 4) + sj0 * 16;
        uint32_t dB = dA + TILE_B;
#pragma unroll
        for (int j = 0; j < 4; j++) {
            cp16(dA + j * 16, Ag + (sj0 + j) * 4);
            cp16(dB + j * 16, Bg + (sj0 + j) * 4);
        }
    };

    stage(0, 0); CP_COMMIT();
    stage(1, 1); CP_COMMIT();

    for (int kt = 0; kt < nt; kt++) {
        CP_WAIT1();
        __syncthreads();
        const int slot = kt - (kt / 3) * 3;

        if (kt + 2 < nt) stage((kt + 2) - ((kt + 2) / 3) * 3, kt + 2);
        CP_COMMIT();

        const uint32_t* pa = (const uint32_t*)(smem + slot * STG_B);
        const uint32_t* pb = pa + 128 * TSTR;

#pragma unroll
        for (int ks = 0; ks < 4; ks++) {
            const int k0 = ks * 8;
            uint32_t a[4][4], b[4][2];
#pragma unroll
            for (int mi = 0; mi < 4; mi++) {
                const int mr = wm + mi * 16;
                a[mi][0] = pa[(mr + grp)     * TSTR + k0 + tig];
                a[mi][1] = pa[(mr + grp + 8) * TSTR + k0 + tig];
                a[mi][2] = pa[(mr + grp)     * TSTR + k0 + tig + 4];
                a[mi][3] = pa[(mr + grp + 8) * TSTR + k0 + tig + 4];
            }
#pragma unroll
            for (int nj = 0; nj < 4; nj++) {
                const int nr = wn + nj * 8 + grp;
                b[nj][0] = pb[nr * TSTR + k0 + tig];
                b[nj][1] = pb[nr * TSTR + k0 + tig + 4];
            }
#pragma unroll
            for (int mi = 0; mi < 4; mi++)
#pragma unroll
                for (int nj = 0; nj < 4; nj++) {
                    asm volatile(
                        "mma.sync.aligned.m16n8k8.row.col.f32.tf32.tf32.f32 "
                        "{%0,%1,%2,%3},{%4,%5,%6,%7},{%8,%9},{%0,%1,%2,%3};\n"
                        : "+f"(c[mi][nj][0]), "+f"(c[mi][nj][1]),
                          "+f"(c[mi][nj][2]), "+f"(c[mi][nj][3])
                        : "r"(a[mi][0]), "r"(a[mi][1]), "r"(a[mi][2]), "r"(a[mi][3]),
                          "r"(b[nj][0]), "r"(b[nj][1]));
                }
        }
    }

#pragma unroll
    for (int nj = 0; nj < 4; nj++) {
        int n = bn + wn + nj * 8 + tig * 2;
        float bv0 = bias[n], bv1 = bias[n + 1];
#pragma unroll
        for (int mi = 0; mi < 4; mi++) {
            int m = bm + wm + mi * 16 + grp;
            float2 v0 = make_float2(c[mi][nj][0] + bv0, c[mi][nj][1] + bv1);
            float2 v1 = make_float2(c[mi][nj][2] + bv0, c[mi][nj][3] + bv1);
            *(float2*)(C + (size_t)m * N + n)       = v0;
            *(float2*)(C + (size_t)(m + 8) * N + n) = v1;
        }
    }
}

// ---------------- causal depthwise conv (d_conv=4) + SiLU ------------------
__global__ void conv_silu_kernel(const float* __restrict__ conv_w,
                                 const float* __restrict__ conv_b) {
    int idx = blockIdx.x * blockDim.x + threadIdx.x;
    if (idx >= MROWS * DINNER) return;
    int d = idx & (DINNER - 1);
    int m = idx >> 11;
    int t = m & (SEQ - 1);

    float4 w = *(const float4*)(conv_w + d * 4);
    float acc = conv_b[d];
    const float* src = g_xres + (size_t)m * (2 * DINNER) + d;
    if (t >= 3) acc = fmaf(w.x, src[-3 * 2 * DINNER], acc);
    if (t >= 2) acc = fmaf(w.y, src[-2 * 2 * DINNER], acc);
    if (t >= 1) acc = fmaf(w.z, src[-1 * 2 * DINNER], acc);
    acc = fmaf(w.w, src[0], acc);
    g_xs[idx] = acc / (1.f + __expf(-acc));
}

// ---------------- x_proj ----------------------------------------------------
__global__ __launch_bounds__(256)
void xproj_kernel(const float* __restrict__ W,
                  const float* __restrict__ bias) {
    int lane = threadIdx.x & 31;
    int j    = blockIdx.x * 8 + (threadIdx.x >> 5);
    int m0   = blockIdx.y * 16;

    const float* wrow = W + (size_t)j * DINNER;
    float wr[64];
#pragma unroll
    for (int i = 0; i < 16; i++) {
        float4 v = *(const float4*)(wrow + lane * 4 + i * 128);
        wr[i * 4 + 0] = v.x; wr[i * 4 + 1] = v.y;
        wr[i * 4 + 2] = v.z; wr[i * 4 + 3] = v.w;
    }
    float bj = bias[j];

    for (int mi = 0; mi < 16; mi++) {
        const float* xrow = g_xs + (size_t)(m0 + mi) * DINNER;
        float acc = 0.f;
#pragma unroll
        for (int i = 0; i < 16; i++) {
            float4 x = *(const float4*)(xrow + lane * 4 + i * 128);
            acc = fmaf(x.x, wr[i * 4 + 0], acc);
            acc = fmaf(x.y, wr[i * 4 + 1], acc);
            acc = fmaf(x.z, wr[i * 4 + 2], acc);
            acc = fmaf(x.w, wr[i * 4 + 3], acc);
        }
#pragma unroll
        for (int off = 16; off > 0; off >>= 1)
            acc += __shfl_xor_sync(0xffffffffu, acc, off);
        if (lane == 0) g_xdbl[(size_t)(m0 + mi) * 48 + j] = acc + bj;
    }
}

// ---------------- dt_proj (K=16) + softplus --------------------------------
__global__ __launch_bounds__(256)
void dt_softplus_kernel(const float* __restrict__ Wdt,
                        const float* __restrict__ bdt) {
    __shared__ float xd[32][16];
    int d  = blockIdx.x * 256 + threadIdx.x;
    int m0 = blockIdx.y * 32;

    float w[16];
#pragma unroll
    for (int i = 0; i < 4; i++) {
        float4 v = *(const float4*)(Wdt + (size_t)d * 16 + i * 4);
        w[i * 4 + 0] = v.x; w[i * 4 + 1] = v.y;
        w[i * 4 + 2] = v.z; w[i * 4 + 3] = v.w;
    }
    float bias = bdt[d];

#pragma unroll
    for (int it = 0; it < 2; it++) {
        int lin = threadIdx.x + it * 256;
        int mi  = lin >> 4;
        int r   = lin & 15;
        xd[mi][r] = g_xdbl[(size_t)(m0 + mi) * 48 + r];
    }
    __syncthreads();

    for (int mi = 0; mi < 32; mi++) {
        float acc = bias;
#pragma unroll
        for (int r = 0; r < 16; r++) acc = fmaf(xd[mi][r], w[r], acc);
        float sp = (acc > 20.f) ? acc : log1pf(__expf(acc));
        g_delta[(size_t)(m0 + mi) * DINNER + d] = sp;
    }
}

// ============================================================================
// Chunked scan, d-per-lane mapping (coalesced), h[16] in registers.
// ============================================================================

// ---- K1: per-chunk local scan -> (P[16], H[16]) summaries ----
__global__ __launch_bounds__(128)
void scan_p1(const float* __restrict__ A_log) {
    __shared__ float Bs[CHUNK][16];
    const int d  = blockIdx.x * 128 + threadIdx.x;
    const int ck = blockIdx.y;
    const int b  = blockIdx.z;
    const int t0 = ck * CHUNK;

    for (int idx = threadIdx.x; idx < CHUNK * 16; idx += 128) {
        int r = idx >> 4, c = idx & 15;
        Bs[r][c] = g_xdbl[(size_t)(b * SEQ + t0 + r) * 48 + DTRANK + c];
    }
    __syncthreads();

    float An[16];
#pragma unroll
    for (int n = 0; n < 16; n++) An[n] = -__expf(A_log[d * 16 + n]);

    float h[16];
#pragma unroll
    for (int n = 0; n < 16; n++) h[n] = 0.f;
    float sumdt = 0.f;

    const float* dp = g_delta + (size_t)(b * SEQ + t0) * DINNER + d;
    const float* xp = g_xs    + (size_t)(b * SEQ + t0) * DINNER + d;
    for (int i = 0; i < CHUNK; i++) {
        float dt = __ldg(dp), xv = __ldg(xp);
        float u  = dt * xv;
        sumdt += dt;
        const float4* bq = (const float4*)&Bs[i][0];
        float4 b0 = bq[0], b1 = bq[1], b2 = bq[2], b3 = bq[3];
        float Bv[16] = {b0.x, b0.y, b0.z, b0.w, b1.x, b1.y, b1.z, b1.w,
                        b2.x, b2.y, b2.z, b2.w, b3.x, b3.y, b3.z, b3.w};
#pragma unroll
        for (int n = 0; n < 16; n++) {
            float dA = __expf(dt * An[n]);
            h[n] = fmaf(dA, h[n], u * Bv[n]);
        }
        dp += DINNER; xp += DINNER;
    }

    const size_t o = ((size_t)(b * NCHUNK + ck) * DINNER + d) * 16;
    float4* Pq = (float4*)(g_P + o);
    float4* Hq = (float4*)(g_H + o);
#pragma unroll
    for (int q = 0; q < 4; q++) {
        float4 pv, hv;
        pv.x = __expf(An[q*4+0] * sumdt); pv.y = __expf(An[q*4+1] * sumdt);
        pv.z = __expf(An[q*4+2] * sumdt); pv.w = __expf(An[q*4+3] * sumdt);
        hv.x = h[q*4+0]; hv.y = h[q*4+1]; hv.z = h[q*4+2]; hv.w = h[q*4+3];
        Pq[q] = pv; Hq[q] = hv;
    }
}

// ---- K2: cross-chunk combine: h_in per chunk ----
__global__ __launch_bounds__(256)
void scan_p2() {
    int tid = blockIdx.x * 256 + threadIdx.x;   // (b*DINNER + d)*16 + n
    int n    = tid & 15;
    int rest = tid >> 4;
    int d    = rest & (DINNER - 1);
    int b    = rest >> 11;

    const size_t stride = (size_t)DINNER * 16;
    size_t idx = ((size_t)(b * NCHUNK) * DINNER + d) * 16 + n;
    float h = 0.f;
#pragma unroll
    for (int c = 0; c < NCHUNK; c++) {
        g_Hin[idx] = h;
        h = fmaf(g_P[idx], h, g_H[idx]);
        idx += stride;
    }
}

// ---- K3: re-scan with h_in, produce gated y (tf32-rounded) ----
__global__ __launch_bounds__(128)
void scan_p3(const float* __restrict__ A_log, const float* __restrict__ Dp) {
    __shared__ float Bs[CHUNK][16];
    __shared__ float Cs[CHUNK][16];
    const int d  = blockIdx.x * 128 + threadIdx.x;
    const int ck = blockIdx.y;
    const int b  = blockIdx.z;
    const int t0 = ck * CHUNK;

    for (int idx = threadIdx.x; idx < CHUNK * 16; idx += 128) {
        int r = idx >> 4, c = idx & 15;
        size_t rowo = (size_t)(b * SEQ + t0 + r) * 48;
        Bs[r][c] = g_xdbl[rowo + DTRANK + c];
        Cs[r][c] = g_xdbl[rowo + DTRANK + DSTATE + c];
    }
    __syncthreads();

    float An[16];
#pragma unroll
    for (int n = 0; n < 16; n++) An[n] = -__expf(A_log[d * 16 + n]);
    const float Dv = Dp[d];

    float h[16];
    {
        const size_t o = ((size_t)(b * NCHUNK + ck) * DINNER + d) * 16;
        const float4* Hq = (const float4*)(g_Hin + o);
#pragma unroll
        for (int q = 0; q < 4; q++) {
            float4 v = Hq[q];
            h[q*4+0] = v.x; h[q*4+1] = v.y; h[q*4+2] = v.z; h[q*4+3] = v.w;
        }
    }

    const float* dp = g_delta + (size_t)(b * SEQ + t0) * DINNER + d;
    const float* xp = g_xs    + (size_t)(b * SEQ + t0) * DINNER + d;
    const float* rp = g_xres  + (size_t)(b * SEQ + t0) * (2 * DINNER) + DINNER + d;
    float*       yp = g_y     + (size_t)(b * SEQ + t0) * DINNER + d;

    for (int i = 0; i < CHUNK; i++) {
        float dt = __ldg(dp), xv = __ldg(xp);
        float u  = dt * xv;
        const float4* bq = (const float4*)&Bs[i][0];
        const float4* cq = (const float4*)&Cs[i][0];
        float4 b0 = bq[0], b1 = bq[1], b2 = bq[2], b3 = bq[3];
        float4 c0 = cq[0], c1 = cq[1], c2 = cq[2], c3 = cq[3];
        float Bv[16] = {b0.x, b0.y, b0.z, b0.w, b1.x, b1.y, b1.z, b1.w,
                        b2.x, b2.y, b2.z, b2.w, b3.x, b3.y, b3.z, b3.w};
        float Cv[16] = {c0.x, c0.y, c0.z, c0.w, c1.x, c1.y, c1.z, c1.w,
                        c2.x, c2.y, c2.z, c2.w, c3.x, c3.y, c3.z, c3.w};
        float y = 0.f;
#pragma unroll
        for (int n = 0; n < 16; n++) {
            float dA = __expf(dt * An[n]);
            h[n] = fmaf(dA, h[n], u * Bv[n]);
            y = fmaf(h[n], Cv[n], y);
        }
        float r = __ldg(rp);
        float g = r / (1.f + __expf(-r));
        *yp = rnd_tf32((y + xv * Dv) * g);

        dp += DINNER; xp += DINNER; rp += 2 * DINNER; yp += DINNER;
    }
}

// ---------------- launch ----------------------------------------------------
extern "C" void kernel_launch(void* const* d_in, const int* in_sizes, int n_in,
                              void* d_out, int out_size) {
    const float* x        = (const float*)d_in[0];
    const float* in_w     = (const float*)d_in[1];
    const float* in_b     = (const float*)d_in[2];
    const float* conv_w   = (const float*)d_in[3];
    const float* conv_b   = (const float*)d_in[4];
    const float* xproj_w  = (const float*)d_in[5];
    const float* xproj_b  = (const float*)d_in[6];
    const float* dt_w     = (const float*)d_in[7];
    const float* dt_b     = (const float*)d_in[8];
    const float* A_log    = (const float*)d_in[9];
    const float* Dp       = (const float*)d_in[10];
    const float* out_w    = (const float*)d_in[11];
    const float* out_b    = (const float*)d_in[12];
    float* out = (float*)d_out;

    float *p_xres, *p_y, *p_x32, *p_wi32, *p_wo32;
    cudaGetSymbolAddress((void**)&p_xres, g_xres);
    cudaGetSymbolAddress((void**)&p_y, g_y);
    cudaGetSymbolAddress((void**)&p_x32, g_x32);
    cudaGetSymbolAddress((void**)&p_wi32, g_wi32);
    cudaGetSymbolAddress((void**)&p_wo32, g_wo32);

    cudaFuncSetAttribute(gemm_tf32_ca,
                         cudaFuncAttributeMaxDynamicSharedMemorySize, GEMM_SMEM);

    // 0) pre-round GEMM operands to tf32
    {
        int n4;
        n4 = MROWS * DMODEL / 4;
        round_tf32_kernel<<<(n4 + 255) / 256, 256>>>(x, p_x32, n4);
        n4 = 2 * DINNER * DMODEL / 4;
        round_tf32_kernel<<<(n4 + 255) / 256, 256>>>(in_w, p_wi32, n4);
        n4 = DMODEL * DINNER / 4;
        round_tf32_kernel<<<(n4 + 255) / 256, 256>>>(out_w, p_wo32, n4);
    }
    // 1) in_proj
    {
        dim3 grid(2 * DINNER / 128, MROWS / 128);
        gemm_tf32_ca<<<grid, 256, GEMM_SMEM>>>(p_x32, p_wi32, in_b, p_xres,
                                               MROWS, 2 * DINNER, DMODEL);
    }
    // 2) conv + silu
    {
        int total = MROWS * DINNER;
        conv_silu_kernel<<<(total + 255) / 256, 256>>>(conv_w, conv_b);
    }
    // 3) x_proj
    {
        dim3 grid(6, MROWS / 16);
        xproj_kernel<<<grid, 256>>>(xproj_w, xproj_b);
    }
    // 4) dt_proj + softplus
    {
        dim3 grid(DINNER / 256, MROWS / 32);
        dt_softplus_kernel<<<grid, 256>>>(dt_w, dt_b);
    }
    // 5) chunked selective scan (3 kernels)
    {
        dim3 grid(DINNER / 128, NCHUNK, BATCH);
        scan_p1<<<grid, 128>>>(A_log);
        scan_p2<<<(BATCH * DINNER * DSTATE) / 256, 256>>>();
        scan_p3<<<grid, 128>>>(A_log, Dp);
    }
    // 6) out_proj
    {
        dim3 grid(DMODEL / 128, MROWS / 128);
        gemm_tf32_ca<<<grid, 256, GEMM_SMEM>>>(p_y, p_wo32, out_b, out,
                                               MROWS, DMODEL, DINNER);
    }
}